// round 10
// baseline (speedup 1.0000x reference)
#include <cuda_runtime.h>
#include <cstdint>
#include <cstddef>

#define NN 100000
#define NE 600000
#define D  128
#define NR 16
#define NB 8
#define EG 16                 // edges per warp-group
#define NW 8                  // warps per CTA
#define NCTA 148

// ---------------- scratch (device globals only) ----------------
__device__ float g_W[(NR + 1) * D * D];   // 16 relation matrices + transposed w_self
__device__ int   g_bucket[NE];
__device__ int   g_cnt[NR];
__device__ int   g_off[NR];               // edge bucket offsets
__device__ int   g_pos[NR];
__device__ int   g_goff[NR + 2];          // group offsets (relations 0..15, self=16)
__device__ int   g_is64;

// ---------------- helpers ----------------
__device__ __forceinline__ unsigned long long fma2(unsigned long long a,
                                                   unsigned long long b,
                                                   unsigned long long c) {
    unsigned long long d;
    asm("fma.rn.f32x2 %0, %1, %2, %3;" : "=l"(d) : "l"(a), "l"(b), "l"(c));
    return d;
}
__device__ __forceinline__ unsigned long long pack2(float v) {
    unsigned long long d;
    unsigned int u = __float_as_uint(v);
    asm("mov.b64 %0, {%1, %2};" : "=l"(d) : "r"(u), "r"(u));
    return d;
}
__device__ __forceinline__ long long ld_idx(const void* p, int i, int is64) {
    return is64 ? ((const long long*)p)[i] : (long long)((const int*)p)[i];
}

// ---------------- prep kernels ----------------
__global__ void k_detect(const void* etype_raw) {
    if (threadIdx.x == 0 && blockIdx.x == 0) {
        const int* p = (const int*)etype_raw;
        int is64 = 1;
        for (int i = 1; i < 2000; i += 2)
            if (p[i] != 0) { is64 = 0; break; }
        g_is64 = is64;
    }
}

__global__ void k_weights(const float* __restrict__ bases,
                          const float* __restrict__ coeff,
                          const float* __restrict__ wself) {
    int idx = blockIdx.x * blockDim.x + threadIdx.x;
    const int total = (NR + 1) * D * D;
    if (idx >= total) return;
    int r  = idx / (D * D);
    int ko = idx - r * (D * D);
    if (r < NR) {
        float s = 0.f;
#pragma unroll
        for (int b = 0; b < NB; b++)
            s += coeff[r * NB + b] * bases[b * D * D + ko];
        g_W[idx] = s;
    } else {
        int k = ko >> 7, o = ko & 127;
        g_W[idx] = wself[o * D + k];
    }
}

__global__ void k_zero_cnt() {
    if (threadIdx.x < NR) g_cnt[threadIdx.x] = 0;
}

__global__ void k_hist(const void* __restrict__ etype) {
    __shared__ int h[NR];
    if (threadIdx.x < NR) h[threadIdx.x] = 0;
    __syncthreads();
    const int is64 = g_is64;
    for (int e = blockIdx.x * blockDim.x + threadIdx.x; e < NE;
         e += gridDim.x * blockDim.x) {
        unsigned rel = (unsigned)ld_idx(etype, e, is64);
        if (rel < NR) atomicAdd(&h[rel], 1);
    }
    __syncthreads();
    if (threadIdx.x < NR) atomicAdd(&g_cnt[threadIdx.x], h[threadIdx.x]);
}

__global__ void k_scan() {
    if (threadIdx.x == 0) {
        int acc = 0, gacc = 0;
        for (int r = 0; r < NR; r++) {
            g_off[r] = acc; g_pos[r] = acc;
            g_goff[r] = gacc;
            acc  += g_cnt[r];
            gacc += (g_cnt[r] + EG - 1) / EG;
        }
        g_goff[NR]     = gacc;                       // self segment start
        g_goff[NR + 1] = gacc + (NN + EG - 1) / EG;  // total
    }
}

__global__ void k_scatter(const void* __restrict__ etype) {
    __shared__ int h[NR];
    __shared__ int base[NR];
    if (threadIdx.x < NR) { h[threadIdx.x] = 0; base[threadIdx.x] = 0; }
    __syncthreads();
    const int is64 = g_is64;
    int e = blockIdx.x * blockDim.x + threadIdx.x;
    int rel = 0, rank = 0;
    bool ok = false;
    if (e < NE) {
        unsigned rr = (unsigned)ld_idx(etype, e, is64);
        if (rr < NR) { rel = (int)rr; ok = true; rank = atomicAdd(&h[rel], 1); }
    }
    __syncthreads();
    if (threadIdx.x < NR && h[threadIdx.x] > 0)
        base[threadIdx.x] = atomicAdd(&g_pos[threadIdx.x], h[threadIdx.x]);
    __syncthreads();
    if (ok) g_bucket[base[rel] + rank] = e;
}

__global__ void k_zero_out(float4* __restrict__ out) {
    const int n = NN * D / 4;
    for (int i = blockIdx.x * blockDim.x + threadIdx.x; i < n;
         i += gridDim.x * blockDim.x)
        out[i] = make_float4(0.f, 0.f, 0.f, 0.f);
}

// ---------------- unified apply kernel ----------------
// 256 threads (8 warps), persistent chunk of groups per CTA. Each warp-group
// = 16 sources (edges of one relation, or self rows for r==16).
// SMEM: 64KB weights + 8 warps * 16 edges * 128 k * 8B dup-f32x2 = 192KB.
// Crossbar per 2k per warp: 2x LDS.128 weights (8 cyc) + 16x 16B-broadcast
// LDS.128 (16 cyc) = 24 cyc for 16 edges -> 0.75 cyc/edge/k.
#define SMEM_BYTES (65536 + NW * EG * D * 8)

__global__ void __launch_bounds__(NW * 32, 1)
k_apply(const float* __restrict__ x,
        const void* __restrict__ eidx,
        float* __restrict__ out) {
    extern __shared__ unsigned long long smbuf[];
    unsigned long long* Wull  = smbuf;           // 8192 ull = 64KB
    unsigned long long* stage = smbuf + 8192;

    __shared__ int s_goff[NR + 2];
    __shared__ int s_off[NR];
    __shared__ int s_cnt[NR];

    const int tid  = threadIdx.x;
    const int warp = tid >> 5, lane = tid & 31;
    const int is64 = g_is64;

    if (tid < NR + 2) s_goff[tid] = g_goff[tid];
    if (tid < NR)     { s_off[tid] = g_off[tid]; s_cnt[tid] = g_cnt[tid]; }
    __syncthreads();

    const int gtotal = s_goff[NR + 1];
    const int chunk  = (gtotal + gridDim.x - 1) / gridDim.x;
    int g0 = blockIdx.x * chunk;
    int g1 = min(g0 + chunk, gtotal);
    if (g0 >= g1) return;

    // find relation containing g0
    int r = 0;
    while (r <= NR && s_goff[r + 1] <= g0) r++;

    unsigned long long* st = stage + warp * (EG * D);   // 16 edges * 128 k
    const ulonglong2* W2 = (const ulonglong2*)Wull;

    while (g0 < g1) {
        const int seg_end = min(g1, s_goff[r + 1]);

        // stage relation r's 128x128 weights (all 256 threads)
        {
            const float4* src = (const float4*)(g_W + r * (D * D));
            float4* dst = (float4*)Wull;
#pragma unroll
            for (int i = 0; i < 16; i++)
                dst[tid + i * 256] = src[tid + i * 256];
        }
        __syncthreads();

        const bool self = (r == NR);
        const int nr    = self ? NN : s_cnt[r];
        const int ebase = self ? 0 : s_off[r];
        const int gbase = s_goff[r];

        for (int gi = g0 + warp; gi < seg_end; gi += NW) {
            const int li = gi - gbase;       // local group index within relation

            // lanes 0..15 fetch metadata for one source each
            int myRow = 0, myCol = 0, myOk = 0;
            if (lane < EG) {
                int ei = li * EG + lane;
                if (ei < nr) {
                    myOk = 1;
                    if (self) {
                        myRow = ei; myCol = ei;
                    } else {
                        int e = g_bucket[ebase + ei];
                        long long rw = ld_idx(eidx, e, is64);
                        long long cl = ld_idx(eidx, NE + e, is64);
                        myRow = (int)(rw < 0 ? 0 : (rw >= NN ? NN - 1 : rw));
                        myCol = (int)(cl < 0 ? 0 : (cl >= NN ? NN - 1 : cl));
                    }
                }
            }
            __syncwarp();

            // stage 16 source rows as duplicated f32x2 pairs
#pragma unroll
            for (int g = 0; g < EG; g++) {
                int col = __shfl_sync(0xffffffffu, myCol, g);
                float4 v = ((const float4*)(x + (size_t)col * D))[lane];
                ulonglong2 p0, p1;
                p0.x = pack2(v.x); p0.y = pack2(v.y);
                p1.x = pack2(v.z); p1.y = pack2(v.w);
                *(ulonglong2*)&st[g * D + lane * 4]     = p0;
                *(ulonglong2*)&st[g * D + lane * 4 + 2] = p1;
            }
            __syncwarp();

            unsigned long long acc[EG][2];
#pragma unroll
            for (int g = 0; g < EG; g++) { acc[g][0] = 0ull; acc[g][1] = 0ull; }

#pragma unroll 2
            for (int k = 0; k < D; k += 2) {
                ulonglong2 wa = W2[k * 32 + lane];         // W[k][lane*4..+3]
                ulonglong2 wb = W2[(k + 1) * 32 + lane];   // W[k+1][...]
#pragma unroll
                for (int g = 0; g < EG; g++) {
                    // one 16B broadcast = dup-pairs for k and k+1
                    ulonglong2 xp = *(const ulonglong2*)&st[g * D + k];
                    acc[g][0] = fma2(xp.x, wa.x, acc[g][0]);
                    acc[g][1] = fma2(xp.x, wa.y, acc[g][1]);
                    acc[g][0] = fma2(xp.y, wb.x, acc[g][0]);
                    acc[g][1] = fma2(xp.y, wb.y, acc[g][1]);
                }
            }

#pragma unroll
            for (int g = 0; g < EG; g++) {
                int ok  = __shfl_sync(0xffffffffu, myOk, g);
                int row = __shfl_sync(0xffffffffu, myRow, g);
                if (ok) {
                    float v0 = __uint_as_float((unsigned int)acc[g][0]);
                    float v1 = __uint_as_float((unsigned int)(acc[g][0] >> 32));
                    float v2 = __uint_as_float((unsigned int)acc[g][1]);
                    float v3 = __uint_as_float((unsigned int)(acc[g][1] >> 32));
                    float* p = out + (size_t)row * D + lane * 4;
                    asm volatile(
                        "red.global.add.v4.f32 [%0], {%1, %2, %3, %4};"
                        :: "l"(p), "f"(v0), "f"(v1), "f"(v2), "f"(v3)
                        : "memory");
                }
            }
            __syncwarp();
        }
        __syncthreads();   // before re-staging weights

        g0 = seg_end;
        r++;
        while (r <= NR && s_goff[r + 1] <= g0) r++;   // skip empty relations
    }
}

// ---------------- launcher ----------------
extern "C" void kernel_launch(void* const* d_in, const int* in_sizes, int n_in,
                              void* d_out, int out_size) {
    // Map inputs by element count (order/dtype-proof): all six counts distinct.
    const float* x     = nullptr;
    const void*  eidx  = nullptr;
    const void*  etype = nullptr;
    const float* bases = nullptr;
    const float* coeff = nullptr;
    const float* wself = nullptr;
    for (int i = 0; i < n_in; i++) {
        switch (in_sizes[i]) {
            case NN * D:      x     = (const float*)d_in[i]; break;
            case 2 * NE:      eidx  = d_in[i];               break;
            case NE:          etype = d_in[i];               break;
            case NB * D * D:  bases = (const float*)d_in[i]; break;
            case NR * NB:     coeff = (const float*)d_in[i]; break;
            case D * D:       wself = (const float*)d_in[i]; break;
            default: break;
        }
    }
    float* out = (float*)d_out;

    cudaFuncSetAttribute((const void*)k_apply,
                         cudaFuncAttributeMaxDynamicSharedMemorySize, SMEM_BYTES);

    k_detect<<<1, 32>>>(etype);
    k_weights<<<((NR + 1) * D * D + 255) / 256, 256>>>(bases, coeff, wself);
    k_zero_cnt<<<1, 32>>>();
    k_hist<<<512, 256>>>(etype);
    k_scan<<<1, 32>>>();
    k_scatter<<<(NE + 255) / 256, 256>>>(etype);
    k_zero_out<<<NCTA, 256>>>((float4*)out);

    k_apply<<<NCTA, NW * 32, SMEM_BYTES>>>(x, eidx, out);
}

// round 13
// speedup vs baseline: 1.8479x; 1.8479x over previous
#include <cuda_runtime.h>
#include <cuda_bf16.h>
#include <cstdint>
#include <cstddef>

#define NN 100000
#define NE 600000
#define D  128
#define NR 16
#define NB 8
#define TM 128                 // tile rows (sources per tile)
#define NSEG (NR + 1)          // 16 relations + self
#define NCTA 148
#define NTH  256               // 8 warps

// ---------------- scratch (device globals only) ----------------
// weights pre-stored in ldmatrix-friendly swizzled [N=128][K=128] bf16 layout
__device__ __nv_bfloat16 g_Wh[NSEG * D * D];
__device__ __nv_bfloat16 g_Wl[NSEG * D * D];
__device__ int g_bucket[NE];
__device__ int g_cnt[NR];
__device__ int g_off[NR];
__device__ int g_pos[NR];
__device__ int g_tgoff[NSEG + 1];
__device__ int g_is64;

// ---------------- helpers ----------------
__device__ __forceinline__ uint32_t smem_u32(const void* p) {
    uint32_t a;
    asm("{ .reg .u64 t; cvta.to.shared.u64 t, %1; cvt.u32.u64 %0, t; }"
        : "=r"(a) : "l"(p));
    return a;
}
// swizzled byte offset for element (row, col) in a 128x128 bf16 tile.
// row stride 256B; 16B chunk index xor'ed with row&7 -> ldmatrix conflict-free.
__device__ __forceinline__ uint32_t sw_off(int row, int col) {
    return (uint32_t)(row * 256 + ((((col >> 3) ^ (row & 7)) & 15) << 4)
                      + ((col & 7) << 1));
}

__device__ __forceinline__ void ldsm_x4(uint32_t& a0, uint32_t& a1,
                                        uint32_t& a2, uint32_t& a3, uint32_t addr) {
    asm volatile("ldmatrix.sync.aligned.m8n8.x4.shared.b16 {%0,%1,%2,%3}, [%4];"
                 : "=r"(a0), "=r"(a1), "=r"(a2), "=r"(a3) : "r"(addr));
}
__device__ __forceinline__ void ldsm_x2(uint32_t& b0, uint32_t& b1, uint32_t addr) {
    asm volatile("ldmatrix.sync.aligned.m8n8.x2.shared.b16 {%0,%1}, [%2];"
                 : "=r"(b0), "=r"(b1) : "r"(addr));
}
__device__ __forceinline__ void mma16816(float* c, uint32_t a0, uint32_t a1,
                                         uint32_t a2, uint32_t a3,
                                         uint32_t b0, uint32_t b1) {
    asm volatile(
        "mma.sync.aligned.m16n8k16.row.col.f32.bf16.bf16.f32 "
        "{%0,%1,%2,%3}, {%4,%5,%6,%7}, {%8,%9}, {%0,%1,%2,%3};"
        : "+f"(c[0]), "+f"(c[1]), "+f"(c[2]), "+f"(c[3])
        : "r"(a0), "r"(a1), "r"(a2), "r"(a3), "r"(b0), "r"(b1));
}

// ---------------- prep kernels (5 launches so ncu -s 5 hits k_apply) --------
__global__ void k_detect(const void* etype_raw) {   // + zero cnt
    if (threadIdx.x < NR) g_cnt[threadIdx.x] = 0;
    if (threadIdx.x == 0 && blockIdx.x == 0) {
        const int* p = (const int*)etype_raw;
        int is64 = 1;
        for (int i = 1; i < 2000; i += 2)
            if (p[i] != 0) { is64 = 0; break; }
        g_is64 = is64;
    }
}

__global__ void k_weights(const float* __restrict__ bases,
                          const float* __restrict__ coeff,
                          const float* __restrict__ wself) {
    int idx = blockIdx.x * blockDim.x + threadIdx.x;
    if (idx >= NSEG * D * D) return;
    int r = idx / (D * D), rem = idx % (D * D);
    int o = rem >> 7, k = rem & 127;        // B[o][k] = W[k][o]
    float w;
    if (r < NR) {
        w = 0.f;
#pragma unroll
        for (int b = 0; b < NB; b++)
            w += coeff[r * NB + b] * bases[b * D * D + k * D + o];
    } else {
        w = wself[o * D + k];               // self: out = x @ w_self^T
    }
    __nv_bfloat16 wh = __float2bfloat16(w);
    __nv_bfloat16 wl = __float2bfloat16(w - __bfloat162float(wh));
    uint32_t off = sw_off(o, k);
    *(__nv_bfloat16*)((char*)g_Wh + (size_t)r * 32768 + off) = wh;
    *(__nv_bfloat16*)((char*)g_Wl + (size_t)r * 32768 + off) = wl;
}

__global__ void k_hist(const void* __restrict__ etype) {
    __shared__ int h[NR];
    if (threadIdx.x < NR) h[threadIdx.x] = 0;
    __syncthreads();
    const int is64 = g_is64;
    for (int e = blockIdx.x * blockDim.x + threadIdx.x; e < NE;
         e += gridDim.x * blockDim.x) {
        unsigned rel = is64 ? (unsigned)((const long long*)etype)[e]
                            : (unsigned)((const int*)etype)[e];
        if (rel < NR) atomicAdd(&h[rel], 1);
    }
    __syncthreads();
    if (threadIdx.x < NR) atomicAdd(&g_cnt[threadIdx.x], h[threadIdx.x]);
}

__global__ void k_scan() {
    if (threadIdx.x == 0) {
        int acc = 0, t = 0;
        for (int r = 0; r < NR; r++) {
            g_off[r] = acc; g_pos[r] = acc;
            g_tgoff[r] = t;
            acc += g_cnt[r];
            t += (g_cnt[r] + TM - 1) / TM;
        }
        g_tgoff[NR] = t;
        t += (NN + TM - 1) / TM;
        g_tgoff[NSEG] = t;
    }
}

__global__ void k_scatter(const void* __restrict__ etype, float4* __restrict__ out) {
    const int nz = NN * D / 4;       // fused: zero output
    for (int i = blockIdx.x * blockDim.x + threadIdx.x; i < nz;
         i += gridDim.x * blockDim.x)
        out[i] = make_float4(0.f, 0.f, 0.f, 0.f);

    __shared__ int h[NR];
    __shared__ int base[NR];
    if (threadIdx.x < NR) { h[threadIdx.x] = 0; base[threadIdx.x] = 0; }
    __syncthreads();
    const int is64 = g_is64;
    int e = blockIdx.x * blockDim.x + threadIdx.x;
    int rel = 0, rank = 0;
    bool ok = false;
    if (e < NE) {
        unsigned rr = is64 ? (unsigned)((const long long*)etype)[e]
                           : (unsigned)((const int*)etype)[e];
        if (rr < NR) { rel = (int)rr; ok = true; rank = atomicAdd(&h[rel], 1); }
    }
    __syncthreads();
    if (threadIdx.x < NR && h[threadIdx.x] > 0)
        base[threadIdx.x] = atomicAdd(&g_pos[threadIdx.x], h[threadIdx.x]);
    __syncthreads();
    if (ok) g_bucket[base[rel] + rank] = e;
}

// ---------------- main tensor-core apply (mma.sync bf16, 3-pass split) ------
// dynamic SMEM (1KB aligned): Ah 32KB | Al 32KB | Bh 32KB | Bl 32KB
#define SM_AH 0
#define SM_AL 32768
#define SM_BH 65536
#define SM_BL 98304
#define SMEM_BYTES (131072 + 1024)

__global__ void __launch_bounds__(NTH, 1)
k_apply(const float* __restrict__ x,
        const void* __restrict__ eidx,
        float* __restrict__ out) {
    extern __shared__ char dynsm[];
    uint32_t rawb = smem_u32(dynsm);
    uint32_t dynbase = (rawb + 1023) & ~1023u;
    char* dynp = dynsm + (dynbase - rawb);

    __shared__ int s_rows[TM];
    __shared__ int s_cols[TM];
    __shared__ int s_cnt[NR], s_off[NR], s_tg[NSEG + 1];

    const int tid = threadIdx.x, wid = tid >> 5, lane = tid & 31;
    const int is64 = g_is64;
    if (tid < NR) { s_cnt[tid] = g_cnt[tid]; s_off[tid] = g_off[tid]; }
    if (tid <= NSEG) s_tg[tid] = g_tgoff[tid];
    __syncthreads();

    const int ntiles = s_tg[NSEG];
    const int chunk  = (ntiles + gridDim.x - 1) / gridDim.x;
    int t0 = blockIdx.x * chunk;
    int t1 = min(t0 + chunk, ntiles);

    int cur_r = -1;
    const uint32_t Ah_b = dynbase + SM_AH, Al_b = dynbase + SM_AL;
    const uint32_t Bh_b = dynbase + SM_BH, Bl_b = dynbase + SM_BL;

    for (int t = t0; t < t1; t++) {
        int r = (cur_r < 0) ? 0 : cur_r;
        while (s_tg[r + 1] <= t) r++;

        __syncthreads();   // prior tile's smem reads / s_rows reads done

        if (r != cur_r) {
            const float4* sh = (const float4*)((const char*)g_Wh + (size_t)r * 32768);
            const float4* sl = (const float4*)((const char*)g_Wl + (size_t)r * 32768);
            float4* dh = (float4*)(dynp + SM_BH);
            float4* dl = (float4*)(dynp + SM_BL);
#pragma unroll
            for (int i = 0; i < 8; i++) {
                dh[tid + i * NTH] = sh[tid + i * NTH];
                dl[tid + i * NTH] = sl[tid + i * NTH];
            }
            cur_r = r;
        }

        const bool self  = (r == NR);
        const int  cnt   = self ? NN : s_cnt[r];
        const int  ebase = self ? 0  : s_off[r];
        const int  lt    = t - s_tg[r];

        // metadata: one source per thread (tids 0..127)
        if (tid < TM) {
            int ei = lt * TM + tid;
            int row = -1, col = -1;
            if (ei < cnt) {
                if (self) { row = ei; col = ei; }
                else {
                    int e = g_bucket[ebase + ei];
                    long long rw = is64 ? ((const long long*)eidx)[e]
                                        : (long long)((const int*)eidx)[e];
                    long long cl = is64 ? ((const long long*)eidx)[NE + e]
                                        : (long long)((const int*)eidx)[NE + e];
                    row = (int)(rw < 0 ? 0 : (rw >= NN ? NN - 1 : rw));
                    col = (int)(cl < 0 ? 0 : (cl >= NN ? NN - 1 : cl));
                }
            }
            s_rows[tid] = row;
            s_cols[tid] = col;
        }
        __syncthreads();

        // gather + hi/lo bf16 split into swizzled A tiles
        {
            char* Ah = dynp + SM_AH;
            char* Al = dynp + SM_AL;
#pragma unroll
            for (int p = 0; p < 2; p++) {
                int rr = (tid >> 2) + p * 64;
                int cc = s_cols[rr];
                const float4* xrow = (const float4*)(x + (size_t)(cc < 0 ? 0 : cc) * D);
#pragma unroll
                for (int j = 0; j < 4; j++) {
                    int q = (tid & 3) + j * 4;          // 16B chunk (8 elems)
                    float4 v0, v1;
                    if (cc >= 0) {
                        v0 = __ldg(xrow + q * 2);
                        v1 = __ldg(xrow + q * 2 + 1);
                    } else {
                        v0 = make_float4(0.f, 0.f, 0.f, 0.f);
                        v1 = v0;
                    }
                    uint32_t h[4], l[4];
                    float4 vv[2] = {v0, v1};
#pragma unroll
                    for (int m = 0; m < 2; m++) {
                        uint32_t h01, h23;
                        asm("cvt.rn.bf16x2.f32 %0, %1, %2;" : "=r"(h01)
                            : "f"(vv[m].y), "f"(vv[m].x));
                        asm("cvt.rn.bf16x2.f32 %0, %1, %2;" : "=r"(h23)
                            : "f"(vv[m].w), "f"(vv[m].z));
                        float hx = __uint_as_float(h01 << 16);
                        float hy = __uint_as_float(h01 & 0xffff0000u);
                        float hz = __uint_as_float(h23 << 16);
                        float hw = __uint_as_float(h23 & 0xffff0000u);
                        uint32_t l01, l23;
                        asm("cvt.rn.bf16x2.f32 %0, %1, %2;" : "=r"(l01)
                            : "f"(vv[m].y - hy), "f"(vv[m].x - hx));
                        asm("cvt.rn.bf16x2.f32 %0, %1, %2;" : "=r"(l23)
                            : "f"(vv[m].w - hw), "f"(vv[m].z - hz));
                        h[m * 2] = h01; h[m * 2 + 1] = h23;
                        l[m * 2] = l01; l[m * 2 + 1] = l23;
                    }
                    uint32_t off = sw_off(rr, q * 8);
                    *(uint4*)(Ah + off) = make_uint4(h[0], h[1], h[2], h[3]);
                    *(uint4*)(Al + off) = make_uint4(l[0], l[1], l[2], l[3]);
                }
            }
        }
        __syncthreads();

        // ---- mma mainloop: warp wid owns M rows [16w, 16w+16) ----
        float acc[16][4];
#pragma unroll
        for (int n = 0; n < 16; n++)
#pragma unroll
            for (int q = 0; q < 4; q++) acc[n][q] = 0.f;

        const int arow = wid * 16 + (lane & 15);
        const int achk = (lane >> 4);                // 0 or 1
        const int bn   = lane & 7;                    // B row within 8-block
        const int bchk = (lane >> 3) & 1;             // k half

#pragma unroll
        for (int kb = 0; kb < 8; kb++) {
            uint32_t aoff = sw_off(arow, (kb * 2 + achk) * 8);
            uint32_t ah0, ah1, ah2, ah3, al0, al1, al2, al3;
            ldsm_x4(ah0, ah1, ah2, ah3, Ah_b + aoff);
            ldsm_x4(al0, al1, al2, al3, Al_b + aoff);
#pragma unroll
            for (int n = 0; n < 16; n++) {
                uint32_t boff = sw_off(n * 8 + bn, (kb * 2 + bchk) * 8);
                uint32_t bh0, bh1, bl0, bl1;
                ldsm_x2(bh0, bh1, Bh_b + boff);
                ldsm_x2(bl0, bl1, Bl_b + boff);
                mma16816(acc[n], ah0, ah1, ah2, ah3, bh0, bh1);
                mma16816(acc[n], al0, al1, al2, al3, bh0, bh1);
                mma16816(acc[n], ah0, ah1, ah2, ah3, bl0, bl1);
            }
        }

        // ---- epilogue: D frag (m = l/4 [+8], n = nb*8 + (l%4)*2) ----
        {
            int r0 = s_rows[wid * 16 + (lane >> 2)];
            int r1 = s_rows[wid * 16 + (lane >> 2) + 8];
            int cb = (lane & 3) * 2;
#pragma unroll
            for (int n = 0; n < 16; n++) {
                int col = n * 8 + cb;
                if (r0 >= 0)
                    asm volatile("red.global.add.v2.f32 [%0], {%1, %2};"
                                 :: "l"(out + (size_t)r0 * D + col),
                                    "f"(acc[n][0]), "f"(acc[n][1]) : "memory");
                if (r1 >= 0)
                    asm volatile("red.global.add.v2.f32 [%0], {%1, %2};"
                                 :: "l"(out + (size_t)r1 * D + col),
                                    "f"(acc[n][2]), "f"(acc[n][3]) : "memory");
            }
        }
    }
}

// ---------------- launcher ----------------
extern "C" void kernel_launch(void* const* d_in, const int* in_sizes, int n_in,
                              void* d_out, int out_size) {
    // map inputs by element count (order/dtype-proof): all six counts distinct
    const float* x     = nullptr;
    const void*  eidx  = nullptr;
    const void*  etype = nullptr;
    const float* bases = nullptr;
    const float* coeff = nullptr;
    const float* wself = nullptr;
    for (int i = 0; i < n_in; i++) {
        switch (in_sizes[i]) {
            case NN * D:      x     = (const float*)d_in[i]; break;
            case 2 * NE:      eidx  = d_in[i];               break;
            case NE:          etype = d_in[i];               break;
            case NB * D * D:  bases = (const float*)d_in[i]; break;
            case NR * NB:     coeff = (const float*)d_in[i]; break;
            case D * D:       wself = (const float*)d_in[i]; break;
            default: break;
        }
    }
    float* out = (float*)d_out;

    cudaFuncSetAttribute((const void*)k_apply,
                         cudaFuncAttributeMaxDynamicSharedMemorySize, SMEM_BYTES);

    k_detect<<<1, 32>>>(etype);
    k_weights<<<(NSEG * D * D + 255) / 256, 256>>>(bases, coeff, wself);
    k_hist<<<512, 256>>>(etype);
    k_scan<<<1, 32>>>();
    k_scatter<<<(NE + 255) / 256, 256>>>(etype, (float4*)out);

    k_apply<<<NCTA, NTH, SMEM_BYTES>>>(x, eidx, out);
}